// round 16
// baseline (speedup 1.0000x reference)
#include <cuda_runtime.h>
#include <cuda_fp16.h>
#include <stdint.h>
#include <math.h>

#define EPSV 1e-8f
#define DD 512
#define MR 8192
#define NR 8192
#define BM 128
#define BN 128
#define BK 64            // fp16 elements per pipeline step (128 B per row)
#define STAGES 3
#define SSTEPS 8         // 512 / 64
#define NTHREADS 128     // 4 warps, 2x2 grid of 64x64 warp tiles
#define TILE_BYTES 16384 // 128 rows x 128 B, swizzled

// ---------------- device scratch (allocation-free) ----------------
// tiled + SW128-pre-swizzled: [rowTile][kstep][128 rows x 128 B]
__device__ __align__(128) __half g_a[(size_t)MR * DD];   // x2
__device__ __align__(128) __half g_b[(size_t)NR * DD];   // x1
__device__ float g_na[MR];
__device__ float g_nb[NR];

__device__ __forceinline__ uint32_t smem_u32(const void* p) {
    uint32_t a;
    asm("{ .reg .u64 t; cvta.to.shared.u64 t, %1; cvt.u32.u64 %0, t; }" : "=r"(a) : "l"(p));
    return a;
}

#define BULK_G2S(dst, src, bytes, mbar) \
    asm volatile("cp.async.bulk.shared::cluster.global.mbarrier::complete_tx::bytes " \
                 "[%0], [%1], %2, [%3];" \
                 :: "r"(dst), "l"(src), "r"((uint32_t)(bytes)), "r"(mbar) : "memory")

#define MBAR_INIT(mbar, cnt) \
    asm volatile("mbarrier.init.shared.b64 [%0], %1;" :: "r"(mbar), "r"((uint32_t)(cnt)) : "memory")
#define MBAR_EXPECT_TX(mbar, bytes) \
    asm volatile("mbarrier.arrive.expect_tx.shared.b64 _, [%0], %1;" \
                 :: "r"(mbar), "r"((uint32_t)(bytes)) : "memory")

#define MBAR_WAIT(mbar, parity) do {                                              \
    uint32_t _m = (mbar); uint32_t _p = (parity); uint32_t _done;                 \
    asm volatile("{\n\t.reg .pred p;\n\t"                                         \
        "mbarrier.try_wait.parity.acquire.cta.shared::cta.b64 p, [%1], %2;\n\t"   \
        "selp.b32 %0, 1, 0, p;\n\t}"                                              \
        : "=r"(_done) : "r"(_m), "r"(_p) : "memory");                             \
    if (!_done) {                                                                 \
        asm volatile("{\n\t.reg .pred P1;\n\t"                                    \
            "WL_%=:\n\t"                                                          \
            "mbarrier.try_wait.parity.acquire.cta.shared::cta.b64 P1, [%0], %1, 0x989680;\n\t" \
            "@P1 bra.uni WD_%=;\n\t"                                              \
            "bra.uni WL_%=;\n\t"                                                  \
            "WD_%=:\n\t}" :: "r"(_m), "r"(_p) : "memory");                        \
    }                                                                             \
} while (0)

#define LDSM_X4(r0, r1, r2, r3, addr) \
    asm volatile("ldmatrix.sync.aligned.m8n8.x4.shared.b16 {%0,%1,%2,%3}, [%4];" \
                 : "=r"(r0), "=r"(r1), "=r"(r2), "=r"(r3) : "r"(addr))

#define MMA16816(d, a, b0, b1) \
    asm volatile("mma.sync.aligned.m16n8k16.row.col.f32.f16.f16.f32 " \
                 "{%0,%1,%2,%3}, {%4,%5,%6,%7}, {%8,%9}, {%0,%1,%2,%3};" \
                 : "+f"((d)[0]), "+f"((d)[1]), "+f"((d)[2]), "+f"((d)[3]) \
                 : "r"((a)[0]), "r"((a)[1]), "r"((a)[2]), "r"((a)[3]), "r"(b0), "r"(b1))

// ---------------- prep: fp32 -> fp16, tiled + SW128 swizzled, + norms ------
// one block (128 threads) per row
__global__ void prep_kernel(const float* __restrict__ x1, const float* __restrict__ x2) {
    int r = blockIdx.x;
    const float* src;
    __half* dst;
    float* nrm;
    int row;
    if (r < NR) { src = x1; dst = g_b; nrm = g_nb; row = r; }
    else        { src = x2; dst = g_a; nrm = g_na; row = r - NR; }

    const float4* p = reinterpret_cast<const float4*>(src + (size_t)row * DD);
    float4 v = p[threadIdx.x];
    float s = v.x * v.x + v.y * v.y + v.z * v.z + v.w * v.w;

    // tiled-swizzled destination
    const int tile = row >> 7;          // row-tile index
    const int tr = row & 127;           // row within tile
    const int c0 = threadIdx.x * 4;     // first fp16 col
    const int ks = c0 >> 6;             // k-step
    const int kc = c0 & 63;             // col within k-step
    // byte offset within tile, SW128: XOR 16B-column by row%8
    uint32_t off = (uint32_t)(tr * 128 + ((kc * 2) ^ ((tr & 7) << 4)));
    char* dp = reinterpret_cast<char*>(dst) + ((size_t)(tile * SSTEPS + ks) << 14) + off;
    __half2 h01 = __floats2half2_rn(v.x, v.y);
    __half2 h23 = __floats2half2_rn(v.z, v.w);
    uint32_t u01 = *reinterpret_cast<uint32_t*>(&h01);
    uint32_t u23 = *reinterpret_cast<uint32_t*>(&h23);
    uint64_t pack = (uint64_t)u01 | ((uint64_t)u23 << 32);
    *reinterpret_cast<uint64_t*>(dp) = pack;   // 8B chunk: same swizzle term

#pragma unroll
    for (int off2 = 16; off2 > 0; off2 >>= 1)
        s += __shfl_down_sync(0xffffffffu, s, off2);
    __shared__ float ws[4];
    if ((threadIdx.x & 31) == 0) ws[threadIdx.x >> 5] = s;
    __syncthreads();
    if (threadIdx.x == 0)
        nrm[row] = sqrtf(ws[0] + ws[1] + ws[2] + ws[3]);
}

// ---------------- GEMM: bulk-copy pipeline + mma.sync + cosine epilogue ----
__global__ void __launch_bounds__(NTHREADS, 2)
cosine_mma_kernel(float* __restrict__ C) {
    extern __shared__ __align__(16) char smem_raw[];
    uint32_t sb0 = smem_u32(smem_raw);
    const uint32_t sbase = (sb0 + 1023u) & ~1023u;   // 1KB-align tiles
    const int tid = threadIdx.x;
    const int wid = tid >> 5;
    const int lid = tid & 31;
    const int bm = blockIdx.y * BM;
    const int bn = blockIdx.x * BN;

    __shared__ __align__(8) uint64_t mbar[STAGES];
    __shared__ float s_na[BM], s_nb[BN];
    s_na[tid] = g_na[bm + tid];
    s_nb[tid] = g_nb[bn + tid];

    uint32_t mb[STAGES];
#pragma unroll
    for (int i = 0; i < STAGES; i++) mb[i] = smem_u32(&mbar[i]);

    if (tid == 0) {
#pragma unroll
        for (int i = 0; i < STAGES; i++) MBAR_INIT(mb[i], 1);
    }
    __syncthreads();

    const char* asrc = reinterpret_cast<const char*>(g_a) + ((size_t)(blockIdx.y * SSTEPS) << 14);
    const char* bsrc = reinterpret_cast<const char*>(g_b) + ((size_t)(blockIdx.x * SSTEPS) << 14);

    // prologue: stages for t=0,1 in flight
    if (tid == 0) {
#pragma unroll
        for (int t = 0; t < 2; t++) {
            uint32_t slot = t % STAGES;
            uint32_t dst = sbase + slot * (2 * TILE_BYTES);
            MBAR_EXPECT_TX(mb[slot], 2 * TILE_BYTES);
            BULK_G2S(dst, asrc + ((size_t)t << 14), TILE_BYTES, mb[slot]);
            BULK_G2S(dst + TILE_BYTES, bsrc + ((size_t)t << 14), TILE_BYTES, mb[slot]);
        }
    }

    const int wm = (wid & 1) * 64;   // 2 warps along M
    const int wn = (wid >> 1) * 64;  // 2 warps along N

    float acc[4][8][4];
#pragma unroll
    for (int i = 0; i < 4; i++)
#pragma unroll
        for (int j = 0; j < 8; j++)
#pragma unroll
            for (int q = 0; q < 4; q++)
                acc[i][j][q] = 0.0f;

    // lane-constant address pieces (swizzled tile: rows of 128 B)
    const int a_row = wm + ((lid >> 3) & 1) * 8 + (lid & 7);
    const int a_kofb = (((lid >> 4) & 1) * 8) * 2;        // 0 or 16 bytes
    const int a_xor = (a_row & 7) << 4;
    const uint32_t a_off = (uint32_t)a_row * 128;
    const int b_row = wn + ((lid >> 4) & 1) * 8 + (lid & 7);
    const int b_kofb = (((lid >> 3) & 1) * 8) * 2;
    const int b_xor = (b_row & 7) << 4;
    const uint32_t b_off = (uint32_t)b_row * 128;

    for (int s = 0; s < SSTEPS; s++) {
        // producer: issue loads for step s+2 into slot (s+2)%3 (freed by the
        // barrier that ended step s-1, which this thread has passed)
        if (tid == 0 && s + 2 < SSTEPS) {
            int t = s + 2;
            uint32_t slot = t % STAGES;
            uint32_t dst = sbase + slot * (2 * TILE_BYTES);
            MBAR_EXPECT_TX(mb[slot], 2 * TILE_BYTES);
            BULK_G2S(dst, asrc + ((size_t)t << 14), TILE_BYTES, mb[slot]);
            BULK_G2S(dst + TILE_BYTES, bsrc + ((size_t)t << 14), TILE_BYTES, mb[slot]);
        }

        // consumer: wait for this step's tiles
        MBAR_WAIT(mb[s % STAGES], (s / STAGES) & 1);

        uint32_t abase = sbase + (s % STAGES) * (2 * TILE_BYTES);
        uint32_t bbase = abase + TILE_BYTES;

#pragma unroll
        for (int k16 = 0; k16 < BK / 16; k16++) {
            const int kb = k16 * 32;   // byte offset of this k16 chunk
            uint32_t a[4][4];
#pragma unroll
            for (int mi = 0; mi < 4; mi++) {
                uint32_t addr = abase + a_off + mi * 2048 + (uint32_t)((kb + a_kofb) ^ a_xor);
                LDSM_X4(a[mi][0], a[mi][1], a[mi][2], a[mi][3], addr);
            }
            uint32_t b[4][4];
#pragma unroll
            for (int nj = 0; nj < 4; nj++) {
                uint32_t addr = bbase + b_off + nj * 2048 + (uint32_t)((kb + b_kofb) ^ b_xor);
                LDSM_X4(b[nj][0], b[nj][1], b[nj][2], b[nj][3], addr);
            }
#pragma unroll
            for (int mi = 0; mi < 4; mi++)
#pragma unroll
                for (int ni = 0; ni < 8; ni++)
                    MMA16816(acc[mi][ni], a[mi], b[ni >> 1][(ni & 1) * 2],
                             b[ni >> 1][(ni & 1) * 2 + 1]);
        }

        // all warps done with slot s%3 before producer refills it at step s+1
        __syncthreads();
    }

    // epilogue: cosine divide + store
    const int qrow = lid >> 2;
    const int qcol = (lid & 3) * 2;
#pragma unroll
    for (int mi = 0; mi < 4; mi++) {
        int m0 = wm + mi * 16 + qrow;
        float na0 = s_na[m0];
        float na1 = s_na[m0 + 8];
        float* r0 = C + (size_t)(bm + m0) * NR + bn;
        float* r1 = C + (size_t)(bm + m0 + 8) * NR + bn;
#pragma unroll
        for (int ni = 0; ni < 8; ni++) {
            int n0 = wn + ni * 8 + qcol;
            float nb0 = s_nb[n0], nb1 = s_nb[n0 + 1];
            float2 v0, v1;
            v0.x = __fdividef(acc[mi][ni][0], fmaxf(na0 * nb0, EPSV));
            v0.y = __fdividef(acc[mi][ni][1], fmaxf(na0 * nb1, EPSV));
            v1.x = __fdividef(acc[mi][ni][2], fmaxf(na1 * nb0, EPSV));
            v1.y = __fdividef(acc[mi][ni][3], fmaxf(na1 * nb1, EPSV));
            *reinterpret_cast<float2*>(r0 + n0) = v0;
            *reinterpret_cast<float2*>(r1 + n0) = v1;
        }
    }
}

// ---------------- launch ----------------
extern "C" void kernel_launch(void* const* d_in, const int* in_sizes, int n_in,
                              void* d_out, int out_size) {
    const float* x1 = (const float*)d_in[0];  // [8192, 512] -> n rows
    const float* x2 = (const float*)d_in[1];  // [8192, 512] -> m rows
    float* out = (float*)d_out;               // [8192, 8192]

    const int smem_bytes = STAGES * 2 * TILE_BYTES + 1024;  // 99328
    cudaFuncSetAttribute(cosine_mma_kernel,
                         cudaFuncAttributeMaxDynamicSharedMemorySize, smem_bytes);

    prep_kernel<<<NR + MR, 128>>>(x1, x2);

    dim3 grid(NR / BN, MR / BM);  // (64, 64)
    cosine_mma_kernel<<<grid, NTHREADS, smem_bytes>>>(out);
}

// round 17
// speedup vs baseline: 1.2636x; 1.2636x over previous
#include <cuda_runtime.h>
#include <cuda_fp16.h>
#include <stdint.h>
#include <math.h>

#define EPSV 1e-8f
#define DD 512
#define MR 8192
#define NR 8192
#define BM 128
#define BN 128
#define BK 64            // fp16 elements per pipeline step
#define PADK 72          // padded smem row (144 B) -> conflict-free ldmatrix
#define STAGES 3
#define SSTEPS 8         // 512 / 64
#define NTHREADS 128     // 4 warps, 2x2 grid of 64x64 warp tiles

// ---------------- device scratch (allocation-free) ----------------
__device__ __half g_a[(size_t)MR * DD];   // x2 as fp16
__device__ __half g_b[(size_t)NR * DD];   // x1 as fp16
__device__ float g_na[MR];
__device__ float g_nb[NR];

__device__ __forceinline__ uint32_t smem_u32(const void* p) {
    uint32_t a;
    asm("{ .reg .u64 t; cvta.to.shared.u64 t, %1; cvt.u32.u64 %0, t; }" : "=r"(a) : "l"(p));
    return a;
}

#define CP16(dst, src) \
    asm volatile("cp.async.cg.shared.global [%0], [%1], 16;" :: "r"(dst), "l"(src))
#define CP_COMMIT() asm volatile("cp.async.commit_group;" ::: "memory")
#define CP_WAIT(n)  asm volatile("cp.async.wait_group %0;" :: "n"(n) : "memory")

#define LDSM_X4(r0, r1, r2, r3, addr) \
    asm volatile("ldmatrix.sync.aligned.m8n8.x4.shared.b16 {%0,%1,%2,%3}, [%4];" \
                 : "=r"(r0), "=r"(r1), "=r"(r2), "=r"(r3) : "r"(addr))

#define MMA16816(d, a, b0, b1) \
    asm volatile("mma.sync.aligned.m16n8k16.row.col.f32.f16.f16.f32 " \
                 "{%0,%1,%2,%3}, {%4,%5,%6,%7}, {%8,%9}, {%0,%1,%2,%3};" \
                 : "+f"((d)[0]), "+f"((d)[1]), "+f"((d)[2]), "+f"((d)[3]) \
                 : "r"((a)[0]), "r"((a)[1]), "r"((a)[2]), "r"((a)[3]), "r"(b0), "r"(b1))

// ---------------- prep: fp32 -> fp16 + row norms ----------------
__global__ void prep_kernel(const float* __restrict__ x1, const float* __restrict__ x2) {
    int r = blockIdx.x;
    const float* src;
    __half* dst;
    float* nrm;
    int row;
    if (r < NR) { src = x1; dst = g_b; nrm = g_nb; row = r; }
    else        { src = x2; dst = g_a; nrm = g_na; row = r - NR; }

    const float4* p = reinterpret_cast<const float4*>(src + (size_t)row * DD);
    float4 v = p[threadIdx.x];
    float s = v.x * v.x + v.y * v.y + v.z * v.z + v.w * v.w;

    size_t o = (size_t)row * DD + threadIdx.x * 4;
    *reinterpret_cast<__half2*>(dst + o)     = __floats2half2_rn(v.x, v.y);
    *reinterpret_cast<__half2*>(dst + o + 2) = __floats2half2_rn(v.z, v.w);

#pragma unroll
    for (int off = 16; off > 0; off >>= 1)
        s += __shfl_down_sync(0xffffffffu, s, off);
    __shared__ float ws[4];
    if ((threadIdx.x & 31) == 0) ws[threadIdx.x >> 5] = s;
    __syncthreads();
    if (threadIdx.x == 0)
        nrm[row] = sqrtf(ws[0] + ws[1] + ws[2] + ws[3]);
}

// ---------------- GEMM via mma.sync + cosine epilogue ----------------
#define STAGE_ELEMS ((BM + BN) * PADK)

__device__ __forceinline__ void load_stage(uint32_t sbase, int stage, int s,
                                           int bm, int bn, int tid) {
    const int ko = s * BK;
    uint32_t abase = sbase + stage * STAGE_ELEMS * 2;
    uint32_t bbase = abase + BM * PADK * 2;
#pragma unroll
    for (int h = 0; h < 8; h++) {
        int c = tid + h * NTHREADS;
        int row = c >> 3, seg = c & 7;
        uint32_t dst = abase + (uint32_t)(row * PADK + seg * 8) * 2;
        CP16(dst, g_a + (size_t)(bm + row) * DD + ko + seg * 8);
    }
#pragma unroll
    for (int h = 0; h < 8; h++) {
        int c = tid + h * NTHREADS;
        int row = c >> 3, seg = c & 7;
        uint32_t dst = bbase + (uint32_t)(row * PADK + seg * 8) * 2;
        CP16(dst, g_b + (size_t)(bn + row) * DD + ko + seg * 8);
    }
    CP_COMMIT();
}

__global__ void __launch_bounds__(NTHREADS, 2)
cosine_mma_kernel(float* __restrict__ C) {
    extern __shared__ __align__(16) __half smem[];
    const uint32_t sbase = smem_u32(smem);
    const int tid = threadIdx.x;
    const int wid = tid >> 5;
    const int lid = tid & 31;
    const int bm = blockIdx.y * BM;
    const int bn = blockIdx.x * BN;

    __shared__ float s_na[BM], s_nb[BN];
    s_na[tid] = g_na[bm + tid];
    s_nb[tid] = g_nb[bn + tid];

    const int wm = (wid & 1) * 64;   // 2 warps along M
    const int wn = (wid >> 1) * 64;  // 2 warps along N

    float acc[4][8][4];
#pragma unroll
    for (int i = 0; i < 4; i++)
#pragma unroll
        for (int j = 0; j < 8; j++)
#pragma unroll
            for (int q = 0; q < 4; q++)
                acc[i][j][q] = 0.0f;

    const int a_row = wm + ((lid >> 3) & 1) * 8 + (lid & 7);
    const int a_kof = ((lid >> 4) & 1) * 8;
    const int b_row = wn + ((lid >> 4) & 1) * 8 + (lid & 7);
    const int b_kof = ((lid >> 3) & 1) * 8;

    // prologue: stages 0, 1 in flight
    load_stage(sbase, 0, 0, bm, bn, tid);
    load_stage(sbase, 1, 1, bm, bn, tid);
    CP_WAIT(1);
    __syncthreads();

    // double-buffered fragments
    uint32_t fa[2][4][4], fb[2][4][4];

#pragma unroll 1
    for (int s = 0; s < SSTEPS; s++) {
        const int stage = s % STAGES;

        // issue cp.async for stage s+2 (slot protected by barrier at end of s-1)
        if (s + STAGES - 1 < SSTEPS)
            load_stage(sbase, (s + STAGES - 1) % STAGES, s + STAGES - 1, bm, bn, tid);

        uint32_t abase = sbase + stage * STAGE_ELEMS * 2;
        uint32_t bbase = abase + BM * PADK * 2;

        // preload chunk 0 fragments
#pragma unroll
        for (int mi = 0; mi < 4; mi++) {
            uint32_t addr = abase + (uint32_t)((a_row + mi * 16) * PADK + a_kof) * 2;
            LDSM_X4(fa[0][mi][0], fa[0][mi][1], fa[0][mi][2], fa[0][mi][3], addr);
        }
#pragma unroll
        for (int nj = 0; nj < 4; nj++) {
            uint32_t addr = bbase + (uint32_t)((b_row + nj * 16) * PADK + b_kof) * 2;
            LDSM_X4(fb[0][nj][0], fb[0][nj][1], fb[0][nj][2], fb[0][nj][3], addr);
        }

#pragma unroll
        for (int k16 = 0; k16 < BK / 16; k16++) {
            const int cur = k16 & 1;
            const int nxt = cur ^ 1;
            // prefetch chunk k16+1 BEFORE issuing this chunk's MMAs: the
            // crossbar burst executes under cover of the tensor pipe
            if (k16 + 1 < BK / 16) {
                const int k0 = (k16 + 1) * 16;
#pragma unroll
                for (int mi = 0; mi < 4; mi++) {
                    uint32_t addr = abase + (uint32_t)((a_row + mi * 16) * PADK + k0 + a_kof) * 2;
                    LDSM_X4(fa[nxt][mi][0], fa[nxt][mi][1], fa[nxt][mi][2], fa[nxt][mi][3], addr);
                }
#pragma unroll
                for (int nj = 0; nj < 4; nj++) {
                    uint32_t addr = bbase + (uint32_t)((b_row + nj * 16) * PADK + k0 + b_kof) * 2;
                    LDSM_X4(fb[nxt][nj][0], fb[nxt][nj][1], fb[nxt][nj][2], fb[nxt][nj][3], addr);
                }
            }
#pragma unroll
            for (int mi = 0; mi < 4; mi++)
#pragma unroll
                for (int ni = 0; ni < 8; ni++)
                    MMA16816(acc[mi][ni], fa[cur][mi], fb[cur][ni >> 1][(ni & 1) * 2],
                             fb[cur][ni >> 1][(ni & 1) * 2 + 1]);
        }

        CP_WAIT(1);
        __syncthreads();
    }

    // epilogue: cosine divide + store
    const int qrow = lid >> 2;
    const int qcol = (lid & 3) * 2;
#pragma unroll
    for (int mi = 0; mi < 4; mi++) {
        int m0 = wm + mi * 16 + qrow;
        float na0 = s_na[m0];
        float na1 = s_na[m0 + 8];
        float* r0 = C + (size_t)(bm + m0) * NR + bn;
        float* r1 = C + (size_t)(bm + m0 + 8) * NR + bn;
#pragma unroll
        for (int ni = 0; ni < 8; ni++) {
            int n0 = wn + ni * 8 + qcol;
            float nb0 = s_nb[n0], nb1 = s_nb[n0 + 1];
            float2 v0, v1;
            v0.x = __fdividef(acc[mi][ni][0], fmaxf(na0 * nb0, EPSV));
            v0.y = __fdividef(acc[mi][ni][1], fmaxf(na0 * nb1, EPSV));
            v1.x = __fdividef(acc[mi][ni][2], fmaxf(na1 * nb0, EPSV));
            v1.y = __fdividef(acc[mi][ni][3], fmaxf(na1 * nb1, EPSV));
            *reinterpret_cast<float2*>(r0 + n0) = v0;
            *reinterpret_cast<float2*>(r1 + n0) = v1;
        }
    }
}

// ---------------- launch ----------------
extern "C" void kernel_launch(void* const* d_in, const int* in_sizes, int n_in,
                              void* d_out, int out_size) {
    const float* x1 = (const float*)d_in[0];  // [8192, 512] -> n rows
    const float* x2 = (const float*)d_in[1];  // [8192, 512] -> m rows
    float* out = (float*)d_out;               // [8192, 8192]

    const int smem_bytes = STAGES * STAGE_ELEMS * 2;  // 110592
    cudaFuncSetAttribute(cosine_mma_kernel,
                         cudaFuncAttributeMaxDynamicSharedMemorySize, smem_bytes);

    prep_kernel<<<NR + MR, 128>>>(x1, x2);

    dim3 grid(NR / BN, MR / BM);  // (64, 64)
    cosine_mma_kernel<<<grid, NTHREADS, smem_bytes>>>(out);
}